// round 2
// baseline (speedup 1.0000x reference)
#include <cuda_runtime.h>
#include <cuda_bf16.h>
#include <cstdint>

// Problem constants
#define BB 2
#define SS 2048
#define DD 1024
#define HH 16
#define DH 64
#define ROWS (BB*SS)          // 4096
#define D3  (3*DD)            // 3072
#define D4  (4*DD)            // 4096

// -------------------- scratch (no allocation allowed) --------------------
__device__ float g_h   [ROWS*DD];   // LN output (reused for LN1 and LN2)
__device__ float g_qkv [ROWS*D3];   // QKV projection
__device__ float g_attn[ROWS*DD];   // attention output (heads merged)
__device__ float g_x1  [ROWS*DD];   // x + attn_proj (residual stream)
__device__ float g_ffn [ROWS*D4];   // MLP hidden

// ============================ LayerNorm ============================
// one block (256 threads) per row of 1024 floats; each thread owns one float4
__global__ __launch_bounds__(256) void ln_kernel(
    const float* __restrict__ x, const float* __restrict__ g,
    const float* __restrict__ b, float* __restrict__ out)
{
    __shared__ float red[2][8];
    const int row = blockIdx.x;
    const int tid = threadIdx.x;
    const float4 v = ((const float4*)(x + (size_t)row * DD))[tid];
    float s  = v.x + v.y + v.z + v.w;
    float ss = v.x*v.x + v.y*v.y + v.z*v.z + v.w*v.w;
    #pragma unroll
    for (int o = 16; o; o >>= 1) {
        s  += __shfl_xor_sync(0xffffffffu, s,  o);
        ss += __shfl_xor_sync(0xffffffffu, ss, o);
    }
    const int w = tid >> 5;
    if ((tid & 31) == 0) { red[0][w] = s; red[1][w] = ss; }
    __syncthreads();
    float ts = 0.f, tss = 0.f;
    #pragma unroll
    for (int i = 0; i < 8; i++) { ts += red[0][i]; tss += red[1][i]; }
    const float mu  = ts * (1.0f / DD);
    const float var = tss * (1.0f / DD) - mu * mu;
    const float rs  = rsqrtf(var + 1e-5f);
    const float4 gv = ((const float4*)g)[tid];
    const float4 bv = ((const float4*)b)[tid];
    float4 o;
    o.x = (v.x - mu) * rs * gv.x + bv.x;
    o.y = (v.y - mu) * rs * gv.y + bv.y;
    o.z = (v.z - mu) * rs * gv.z + bv.z;
    o.w = (v.w - mu) * rs * gv.w + bv.w;
    ((float4*)(out + (size_t)row * DD))[tid] = o;
}

// ============================ SGEMM ============================
// C[M,N] = A[M,K] @ B[K,N] + bias  (+ epilogue)
// EPI: 0 = bias, 1 = bias + exact GELU, 2 = bias + residual add
// 128x128 tile, BK=8, 256 threads, 8x8 per-thread microtile.
__device__ __forceinline__ float gelu_exact(float x) {
    return 0.5f * x * (1.0f + erff(x * 0.70710678118654752f));
}

template<int EPI>
__global__ __launch_bounds__(256) void sgemm_kernel(
    int M, int N, int K,
    const float* __restrict__ A, const float* __restrict__ Bm,
    const float* __restrict__ bias, const float* __restrict__ res,
    float* __restrict__ C)
{
    __shared__ float As[8][132];   // A tile transposed, padded
    __shared__ float Bs[8][128];

    const int tid  = threadIdx.x;
    const int crow = blockIdx.y * 128;
    const int ccol = blockIdx.x * 128;

    const int rowA = tid >> 1;            // 0..127
    const int colA = (tid & 1) * 4;       // 0 or 4
    const int rowB = tid >> 5;            // 0..7
    const int colB = (tid & 31) * 4;      // 0..124

    const float* Aptr = A + (size_t)(crow + rowA) * K;
    const float* Bptr = Bm + ccol + colB;

    const int tr = (tid >> 4) * 8;        // thread row within tile
    const int tc = (tid & 15) * 8;        // thread col within tile

    float acc[8][8];
    #pragma unroll
    for (int i = 0; i < 8; i++)
        #pragma unroll
        for (int j = 0; j < 8; j++) acc[i][j] = 0.f;

    for (int k0 = 0; k0 < K; k0 += 8) {
        const float4 av = *(const float4*)(Aptr + k0 + colA);
        As[colA + 0][rowA] = av.x;
        As[colA + 1][rowA] = av.y;
        As[colA + 2][rowA] = av.z;
        As[colA + 3][rowA] = av.w;
        *(float4*)&Bs[rowB][colB] = *(const float4*)(Bptr + (size_t)(k0 + rowB) * N);
        __syncthreads();

        #pragma unroll
        for (int kk = 0; kk < 8; kk++) {
            float4 a0 = *(const float4*)&As[kk][tr];
            float4 a1 = *(const float4*)&As[kk][tr + 4];
            float4 b0 = *(const float4*)&Bs[kk][tc];
            float4 b1 = *(const float4*)&Bs[kk][tc + 4];
            const float ra[8] = {a0.x,a0.y,a0.z,a0.w,a1.x,a1.y,a1.z,a1.w};
            const float rb[8] = {b0.x,b0.y,b0.z,b0.w,b1.x,b1.y,b1.z,b1.w};
            #pragma unroll
            for (int i = 0; i < 8; i++)
                #pragma unroll
                for (int j = 0; j < 8; j++)
                    acc[i][j] += ra[i] * rb[j];
        }
        __syncthreads();
    }

    const int gr = crow + tr;
    const int gc = ccol + tc;
    float bl[8];
    #pragma unroll
    for (int j = 0; j < 8; j++) bl[j] = bias[gc + j];

    #pragma unroll
    for (int i = 0; i < 8; i++) {
        const size_t rowoff = (size_t)(gr + i) * N + gc;
        float v[8];
        #pragma unroll
        for (int j = 0; j < 8; j++) {
            float t = acc[i][j] + bl[j];
            if (EPI == 1) t = gelu_exact(t);
            v[j] = t;
        }
        if (EPI == 2) {
            const float4 r0 = *(const float4*)(res + rowoff);
            const float4 r1 = *(const float4*)(res + rowoff + 4);
            v[0]+=r0.x; v[1]+=r0.y; v[2]+=r0.z; v[3]+=r0.w;
            v[4]+=r1.x; v[5]+=r1.y; v[6]+=r1.z; v[7]+=r1.w;
        }
        *(float4*)(C + rowoff)     = make_float4(v[0],v[1],v[2],v[3]);
        *(float4*)(C + rowoff + 4) = make_float4(v[4],v[5],v[6],v[7]);
    }
}

// ============================ Attention ============================
// Online-softmax flash attention, fp32.
// Block: 256 threads = 32 query rows x 8 lane-groups. grid = (S/32, B*H).
// K and V share one smem buffer (loaded in sequence per 64-key tile).
#define QT 32
#define KT 64
#define QS_STRIDE 68   // multiple of 4 -> float4 ok; conflict-free broadcast reads
#define KV_STRIDE 68
#define PT_STRIDE 33

__global__ __launch_bounds__(256) void attn_kernel(
    const float* __restrict__ qkv, float* __restrict__ out)
{
    __shared__ float Qs[QT * QS_STRIDE];   // 2176 floats
    __shared__ float KVs[KT * KV_STRIDE];  // 4352 floats
    __shared__ float Pt[KT * PT_STRIDE];   // 2112 floats  (scores transposed)

    const int tid = threadIdx.x;
    const int bh  = blockIdx.y;
    const int b   = bh >> 4;
    const int h   = bh & 15;
    const int q0  = blockIdx.x * QT;

    const float* base  = qkv + (size_t)b * SS * D3;
    const float* qbase = base + h * DH;
    const float* kbase = base + DD  + h * DH;
    const float* vbase = base + 2*DD + h * DH;

    // load Q tile: 32 rows x 16 float4
    for (int i = tid; i < QT * 16; i += 256) {
        const int r = i >> 4, c4 = i & 15;
        const float4 v = *(const float4*)(qbase + (size_t)(q0 + r) * D3 + c4 * 4);
        *(float4*)&Qs[r * QS_STRIDE + c4 * 4] = v;
    }

    const int r  = tid >> 3;   // query row within tile (0..31)
    const int kg = tid & 7;    // lane group (0..7)
    const int d0 = kg << 3;    // output dim base for PV phase

    float m = -1e30f, l = 0.f;
    float O[8];
    #pragma unroll
    for (int i = 0; i < 8; i++) O[i] = 0.f;

    for (int t = 0; t < SS / KT; t++) {
        __syncthreads();   // Q visible (t=0); prior PV done reading KVs/Pt
        // load K tile (64 rows x 16 float4)
        for (int i = tid; i < KT * 16; i += 256) {
            const int j = i >> 4, c4 = i & 15;
            *(float4*)&KVs[j * KV_STRIDE + c4 * 4] =
                *(const float4*)(kbase + (size_t)(t * KT + j) * D3 + c4 * 4);
        }
        __syncthreads();

        // scores: this thread handles keys j = jj*8 + kg (lane-consecutive per jj)
        float p[8];
        #pragma unroll
        for (int jj = 0; jj < 8; jj++) p[jj] = 0.f;
        #pragma unroll
        for (int d4 = 0; d4 < DH; d4 += 4) {
            const float4 qv = *(const float4*)&Qs[r * QS_STRIDE + d4];
            #pragma unroll
            for (int jj = 0; jj < 8; jj++) {
                const float4 kv = *(const float4*)&KVs[(jj * 8 + kg) * KV_STRIDE + d4];
                p[jj] += qv.x*kv.x + qv.y*kv.y + qv.z*kv.z + qv.w*kv.w;
            }
        }
        float mloc = -1e30f;
        #pragma unroll
        for (int jj = 0; jj < 8; jj++) { p[jj] *= 0.125f; mloc = fmaxf(mloc, p[jj]); }
        #pragma unroll
        for (int o = 4; o; o >>= 1)
            mloc = fmaxf(mloc, __shfl_xor_sync(0xffffffffu, mloc, o, 8));

        const float mnew = fmaxf(m, mloc);
        const float corr = __expf(m - mnew);
        l *= corr;
        #pragma unroll
        for (int i = 0; i < 8; i++) O[i] *= corr;

        float lloc = 0.f;
        #pragma unroll
        for (int jj = 0; jj < 8; jj++) {
            const float e = __expf(p[jj] - mnew);
            lloc += e;
            Pt[(jj * 8 + kg) * PT_STRIDE + r] = e;
        }
        #pragma unroll
        for (int o = 4; o; o >>= 1)
            lloc += __shfl_xor_sync(0xffffffffu, lloc, o, 8);
        l += lloc;
        m = mnew;

        __syncthreads();   // scores done reading KVs; Pt fully written
        // load V tile into same buffer
        for (int i = tid; i < KT * 16; i += 256) {
            const int j = i >> 4, c4 = i & 15;
            *(float4*)&KVs[j * KV_STRIDE + c4 * 4] =
                *(const float4*)(vbase + (size_t)(t * KT + j) * D3 + c4 * 4);
        }
        __syncthreads();

        // PV: O[d0..d0+7] += sum_j P[r][j] * V[j][d0..]
        #pragma unroll 4
        for (int j = 0; j < KT; j++) {
            const float pj = Pt[j * PT_STRIDE + r];
            const float4 v0 = *(const float4*)&KVs[j * KV_STRIDE + d0];
            const float4 v1 = *(const float4*)&KVs[j * KV_STRIDE + d0 + 4];
            O[0] += pj * v0.x; O[1] += pj * v0.y; O[2] += pj * v0.z; O[3] += pj * v0.w;
            O[4] += pj * v1.x; O[5] += pj * v1.y; O[6] += pj * v1.z; O[7] += pj * v1.w;
        }
    }

    const float inv = 1.0f / l;
    float* op = out + ((size_t)(b * SS + q0 + r)) * DD + h * DH + d0;
    float4 o0 = make_float4(O[0]*inv, O[1]*inv, O[2]*inv, O[3]*inv);
    float4 o1 = make_float4(O[4]*inv, O[5]*inv, O[6]*inv, O[7]*inv);
    *(float4*)op       = o0;
    *(float4*)(op + 4) = o1;
}

// ============================ launch ============================
extern "C" void kernel_launch(void* const* d_in, const int* in_sizes, int n_in,
                              void* d_out, int out_size)
{
    const float* x     = (const float*)d_in[0];
    const float* ln1_g = (const float*)d_in[1];
    const float* ln1_b = (const float*)d_in[2];
    const float* w_qkv = (const float*)d_in[3];
    const float* b_qkv = (const float*)d_in[4];
    const float* w_out = (const float*)d_in[5];
    const float* b_out = (const float*)d_in[6];
    const float* ln2_g = (const float*)d_in[7];
    const float* ln2_b = (const float*)d_in[8];
    const float* w1    = (const float*)d_in[9];
    const float* b1    = (const float*)d_in[10];
    const float* w2    = (const float*)d_in[11];
    const float* b2    = (const float*)d_in[12];

    float *hbuf, *qkvbuf, *attnbuf, *x1buf, *ffnbuf;
    cudaGetSymbolAddress((void**)&hbuf,    g_h);
    cudaGetSymbolAddress((void**)&qkvbuf,  g_qkv);
    cudaGetSymbolAddress((void**)&attnbuf, g_attn);
    cudaGetSymbolAddress((void**)&x1buf,   g_x1);
    cudaGetSymbolAddress((void**)&ffnbuf,  g_ffn);

    // 1) LN1
    ln_kernel<<<ROWS, 256>>>(x, ln1_g, ln1_b, hbuf);
    // 2) QKV projection [4096,1024]x[1024,3072]
    sgemm_kernel<0><<<dim3(D3/128, ROWS/128), 256>>>(ROWS, D3, DD, hbuf, w_qkv, b_qkv, nullptr, qkvbuf);
    // 3) attention
    attn_kernel<<<dim3(SS/QT, BB*HH), 256>>>(qkvbuf, attnbuf);
    // 4) out projection + residual(x)
    sgemm_kernel<2><<<dim3(DD/128, ROWS/128), 256>>>(ROWS, DD, DD, attnbuf, w_out, b_out, x, x1buf);
    // 5) LN2
    ln_kernel<<<ROWS, 256>>>(x1buf, ln2_g, ln2_b, hbuf);
    // 6) MLP up + exact GELU [4096,1024]x[1024,4096]
    sgemm_kernel<1><<<dim3(D4/128, ROWS/128), 256>>>(ROWS, D4, DD, hbuf, w1, b1, nullptr, ffnbuf);
    // 7) MLP down + residual(x1) -> out [4096,4096]x[4096,1024]
    sgemm_kernel<2><<<dim3(DD/128, ROWS/128), 256>>>(ROWS, DD, D4, ffnbuf, w2, b2, x1buf, (float*)d_out);
}

// round 5
// speedup vs baseline: 3.9886x; 3.9886x over previous
#include <cuda_runtime.h>
#include <cuda_bf16.h>
#include <cstdint>

// Problem constants
#define BB 2
#define SS 2048
#define DD 1024
#define HH 16
#define DH 64
#define ROWS (BB*SS)          // 4096
#define D3  (3*DD)            // 3072
#define D4  (4*DD)            // 4096
#define NZ  (BB*HH)           // 32 batched heads

typedef __nv_bfloat16 bf16;

// -------------------- scratch (no allocation allowed) --------------------
__device__ float g_scores[(size_t)NZ*SS*SS];   // 512MB attention scores
__device__ bf16  g_ph[(size_t)NZ*SS*SS];       // softmax P hi
__device__ bf16  g_pl[(size_t)NZ*SS*SS];       // softmax P lo
__device__ bf16  g_qh[NZ*SS*DH], g_ql[NZ*SS*DH];
__device__ bf16  g_kh[NZ*SS*DH], g_kl[NZ*SS*DH];
__device__ bf16  g_vh[NZ*SS*DH], g_vl[NZ*SS*DH];
__device__ float g_x1 [ROWS*DD];               // residual stream after attn
__device__ bf16  g_ah [ROWS*DD], g_al [ROWS*DD];    // activation hi/lo
__device__ bf16  g_a2h[ROWS*D4], g_a2l[ROWS*D4];    // GELU out hi/lo
__device__ bf16  g_bwh[DD*D4],  g_bwl[DD*D4];       // weight split (no transpose)

// ==================== PTX helpers (portable sm_80+ subset) ====================
__device__ __forceinline__ uint32_t smem_u32(const void* p) {
    uint32_t a;
    asm("{ .reg .u64 t; cvta.to.shared.u64 t, %1; cvt.u32.u64 %0, t; }" : "=r"(a) : "l"(p));
    return a;
}
__device__ __forceinline__ void cp16(uint32_t s, const void* g) {
    asm volatile("cp.async.cg.shared.global [%0], [%1], 16;" :: "r"(s), "l"(g));
}
#define CP_COMMIT() asm volatile("cp.async.commit_group;" ::: "memory")
#define CP_WAIT0()  asm volatile("cp.async.wait_group 0;" ::: "memory")
#define CP_WAIT1()  asm volatile("cp.async.wait_group 1;" ::: "memory")

#define LDSM4(R, A) \
    asm volatile("ldmatrix.sync.aligned.m8n8.x4.shared.b16 {%0,%1,%2,%3}, [%4];" \
        : "=r"((R)[0]), "=r"((R)[1]), "=r"((R)[2]), "=r"((R)[3]) : "r"(A))
#define LDSM4T(R, A) \
    asm volatile("ldmatrix.sync.aligned.m8n8.x4.trans.shared.b16 {%0,%1,%2,%3}, [%4];" \
        : "=r"((R)[0]), "=r"((R)[1]), "=r"((R)[2]), "=r"((R)[3]) : "r"(A))
#define MMA(C, A, B) \
    asm volatile("mma.sync.aligned.m16n8k16.row.col.f32.bf16.bf16.f32 " \
        "{%0,%1,%2,%3}, {%4,%5,%6,%7}, {%8,%9}, {%0,%1,%2,%3};" \
        : "+f"((C)[0]), "+f"((C)[1]), "+f"((C)[2]), "+f"((C)[3]) \
        : "r"((A)[0]), "r"((A)[1]), "r"((A)[2]), "r"((A)[3]), "r"((B)[0]), "r"((B)[1]))

// ==================== bf16 split helpers ====================
__device__ __forceinline__ uint32_t pack_bf2(float x, float y) {
    __nv_bfloat162 t = __floats2bfloat162_rn(x, y);
    return *reinterpret_cast<uint32_t*>(&t);
}
__device__ __forceinline__ void split2(float v, unsigned short& h, unsigned short& l) {
    bf16 hb = __float2bfloat16(v);
    bf16 lb = __float2bfloat16(v - __bfloat162float(hb));
    h = *reinterpret_cast<unsigned short*>(&hb);
    l = *reinterpret_cast<unsigned short*>(&lb);
}
__device__ __forceinline__ float gelu_exact(float x) {
    return 0.5f * x * (1.0f + erff(x * 0.70710678118654752f));
}

// ============================ LayerNorm (fused split output) ============================
__global__ __launch_bounds__(256) void ln_split_kernel(
    const float* __restrict__ x, const float* __restrict__ g,
    const float* __restrict__ b, bf16* __restrict__ ohi, bf16* __restrict__ olo)
{
    __shared__ float red[2][8];
    const int row = blockIdx.x;
    const int tid = threadIdx.x;
    const float4 v = ((const float4*)(x + (size_t)row * DD))[tid];
    float s  = v.x + v.y + v.z + v.w;
    float ss = v.x*v.x + v.y*v.y + v.z*v.z + v.w*v.w;
    #pragma unroll
    for (int o = 16; o; o >>= 1) {
        s  += __shfl_xor_sync(0xffffffffu, s,  o);
        ss += __shfl_xor_sync(0xffffffffu, ss, o);
    }
    const int w = tid >> 5;
    if ((tid & 31) == 0) { red[0][w] = s; red[1][w] = ss; }
    __syncthreads();
    float ts = 0.f, tss = 0.f;
    #pragma unroll
    for (int i = 0; i < 8; i++) { ts += red[0][i]; tss += red[1][i]; }
    const float mu  = ts * (1.0f / DD);
    const float var = tss * (1.0f / DD) - mu * mu;
    const float rs  = rsqrtf(var + 1e-5f);
    const float4 gv = ((const float4*)g)[tid];
    const float4 bv = ((const float4*)b)[tid];
    float o[4];
    o[0] = (v.x - mu) * rs * gv.x + bv.x;
    o[1] = (v.y - mu) * rs * gv.y + bv.y;
    o[2] = (v.z - mu) * rs * gv.z + bv.z;
    o[3] = (v.w - mu) * rs * gv.w + bv.w;
    ushort4 h, l;
    split2(o[0], h.x, l.x); split2(o[1], h.y, l.y);
    split2(o[2], h.z, l.z); split2(o[3], h.w, l.w);
    const size_t idx = (size_t)row * DD + tid * 4;
    *(ushort4*)(ohi + idx) = h;
    *(ushort4*)(olo + idx) = l;
}

// ============================ elementwise fp32 -> hi/lo split ============================
__global__ __launch_bounds__(256) void convert_split_kernel(
    const float* __restrict__ in, bf16* __restrict__ ohi, bf16* __restrict__ olo)
{
    const size_t i = ((size_t)blockIdx.x * 256 + threadIdx.x) * 4;
    const float4 v = *(const float4*)(in + i);
    ushort4 h, l;
    split2(v.x, h.x, l.x); split2(v.y, h.y, l.y);
    split2(v.z, h.z, l.z); split2(v.w, h.w, l.w);
    *(ushort4*)(ohi + i) = h;
    *(ushort4*)(olo + i) = l;
}

// ============================ linear GEMM (mma.sync, split bf16, 3 terms) ============================
// C[M,N] = (Ah+Al)[M,K] @ (Bh+Bl)[K,N] + bias (+epilogue)
// Tile 128x128, BK=32, 256 threads = 8 warps (2x4), warp tile 64x32.
// smem per stage: Ah 128x32 pad80B =10240 | Al +10240 | Bh 32x128 pad272B =8704 | Bl +8704 = 37888
// EPI: 1 = bias+GELU->split bf16 out; 2 = bias+residual->fp32; 3 = bias + qkv head-split
#define STG1 37888
#define GEMM_SMEM (2 * STG1)

template<int EPI>
__global__ __launch_bounds__(256) void gemm_mma(
    int M, int N, int K,
    const bf16* __restrict__ Ah, const bf16* __restrict__ Al,
    const bf16* __restrict__ Bh, const bf16* __restrict__ Bl,
    const float* __restrict__ bias, const float* __restrict__ res,
    float* __restrict__ Cf, bf16* __restrict__ Chi, bf16* __restrict__ Clo,
    bf16* __restrict__ qh, bf16* __restrict__ ql,
    bf16* __restrict__ kh, bf16* __restrict__ kl,
    bf16* __restrict__ vh, bf16* __restrict__ vl)
{
    extern __shared__ char sm[];
    const uint32_t smb = smem_u32(sm);
    const int tid = threadIdx.x, lane = tid & 31, wid = tid >> 5;
    const int m0 = blockIdx.y * 128, n0 = blockIdx.x * 128;
    const int wm = wid >> 2, wn = wid & 3;

    float acc[4][4][4];
    #pragma unroll
    for (int i = 0; i < 4; i++)
        #pragma unroll
        for (int j = 0; j < 4; j++)
            #pragma unroll
            for (int q = 0; q < 4; q++) acc[i][j][q] = 0.f;

    const int NSG = K >> 5;

    // stage loader
    auto load_stage = [&](int s, int buf) {
        const uint32_t sb = smb + buf * STG1;
        const int k0 = s << 5;
        #pragma unroll
        for (int t = 0; t < 2; t++) {
            const int i = tid + t * 256;
            const int r = i >> 2, c = i & 3;          // A: 128 rows x 4 chunks
            cp16(sb + r * 80 + c * 16,          Ah + (size_t)(m0 + r) * K + k0 + c * 8);
            cp16(sb + 10240 + r * 80 + c * 16,  Al + (size_t)(m0 + r) * K + k0 + c * 8);
            const int rb = i >> 4, cb = i & 15;       // B: 32 rows x 16 chunks
            cp16(sb + 20480 + rb * 272 + cb * 16,         Bh + (size_t)(k0 + rb) * N + n0 + cb * 8);
            cp16(sb + 20480 + 8704 + rb * 272 + cb * 16,  Bl + (size_t)(k0 + rb) * N + n0 + cb * 8);
        }
        CP_COMMIT();
    };

    load_stage(0, 0);
    for (int s = 0; s < NSG; s++) {
        const int buf = s & 1;
        if (s + 1 < NSG) { load_stage(s + 1, buf ^ 1); CP_WAIT1(); }
        else             { CP_WAIT0(); }
        __syncthreads();

        const uint32_t sA  = smb + buf * STG1;
        const uint32_t sAl = sA + 10240;
        const uint32_t sB  = sA + 20480;
        const uint32_t sBl = sB + 8704;

        #pragma unroll
        for (int ks = 0; ks < 2; ks++) {
            const int kb = ks * 32;
            uint32_t af[4][4], bh_[4][2], bl_[4][2];
            #pragma unroll
            for (int mf = 0; mf < 4; mf++)
                LDSM4(af[mf], sA + (wm*64 + mf*16 + (lane & 15)) * 80 + kb + (lane >> 4) * 16);
            #pragma unroll
            for (int nh = 0; nh < 2; nh++) {
                uint32_t r[4];
                LDSM4T(r, sB + (ks*16 + (lane & 7) + ((lane >> 3) & 1) * 8) * 272
                          + (wn*32 + nh*16) * 2 + (lane >> 4) * 16);
                bh_[nh*2][0]=r[0]; bh_[nh*2][1]=r[1]; bh_[nh*2+1][0]=r[2]; bh_[nh*2+1][1]=r[3];
                LDSM4T(r, sBl + (ks*16 + (lane & 7) + ((lane >> 3) & 1) * 8) * 272
                          + (wn*32 + nh*16) * 2 + (lane >> 4) * 16);
                bl_[nh*2][0]=r[0]; bl_[nh*2][1]=r[1]; bl_[nh*2+1][0]=r[2]; bl_[nh*2+1][1]=r[3];
            }
            #pragma unroll
            for (int mf = 0; mf < 4; mf++)
                #pragma unroll
                for (int nf = 0; nf < 4; nf++) MMA(acc[mf][nf], af[mf], bh_[nf]);
            #pragma unroll
            for (int mf = 0; mf < 4; mf++)
                #pragma unroll
                for (int nf = 0; nf < 4; nf++) MMA(acc[mf][nf], af[mf], bl_[nf]);
            #pragma unroll
            for (int mf = 0; mf < 4; mf++)
                LDSM4(af[mf], sAl + (wm*64 + mf*16 + (lane & 15)) * 80 + kb + (lane >> 4) * 16);
            #pragma unroll
            for (int mf = 0; mf < 4; mf++)
                #pragma unroll
                for (int nf = 0; nf < 4; nf++) MMA(acc[mf][nf], af[mf], bh_[nf]);
        }
        __syncthreads();
    }

    // epilogue
    const int r_base = m0 + wm * 64;
    const int c_base = n0 + wn * 32;
    #pragma unroll
    for (int mf = 0; mf < 4; mf++) {
        #pragma unroll
        for (int nf = 0; nf < 4; nf++) {
            const int row0 = r_base + mf*16 + (lane >> 2);
            const int col  = c_base + nf*8 + (lane & 3) * 2;
            const float b0 = bias[col], b1 = bias[col + 1];
            #pragma unroll
            for (int half = 0; half < 2; half++) {
                const int row = row0 + half * 8;
                float v0 = acc[mf][nf][half*2 + 0] + b0;
                float v1 = acc[mf][nf][half*2 + 1] + b1;
                const size_t off = (size_t)row * N + col;
                if (EPI == 1) {
                    v0 = gelu_exact(v0); v1 = gelu_exact(v1);
                    unsigned short h0,l0,h1,l1;
                    split2(v0, h0, l0); split2(v1, h1, l1);
                    *(uint32_t*)(Chi + off) = (uint32_t)h0 | ((uint32_t)h1 << 16);
                    *(uint32_t*)(Clo + off) = (uint32_t)l0 | ((uint32_t)l1 << 16);
                } else if (EPI == 2) {
                    const float2 rv = *(const float2*)(res + off);
                    *(float2*)(Cf + off) = make_float2(v0 + rv.x, v1 + rv.y);
                } else { // EPI == 3: qkv head split
                    const int which = n0 >> 10;              // uniform per CTA
                    const int h = (col >> 6) & 15;
                    const int d = col & 63;
                    const int bb = row >> 11, s_ = row & 2047;
                    const size_t doff = ((size_t)(bb * HH + h) * SS + s_) * DH + d;
                    bf16 *dh, *dl;
                    if (which == 0)      { dh = qh; dl = ql; }
                    else if (which == 1) { dh = kh; dl = kl; }
                    else                 { dh = vh; dl = vl; }
                    unsigned short h0,l0,h1,l1;
                    split2(v0, h0, l0); split2(v1, h1, l1);
                    *(uint32_t*)(dh + doff) = (uint32_t)h0 | ((uint32_t)h1 << 16);
                    *(uint32_t*)(dl + doff) = (uint32_t)l0 | ((uint32_t)l1 << 16);
                }
            }
        }
    }
}

// ============================ scores GEMM: S = (Q @ K^T) * 0.125 ============================
// batched z=32; M=N=2048, K=64. Tile 128x128, single stage.
// smem: Qh 128x64 pad144B = 18432 | Ql | Kh (as B, [N,K] layout, non-trans) | Kl = 73728
#define SC_SMEM (4 * 18432)
__global__ __launch_bounds__(256) void scores_mma(
    const bf16* __restrict__ qh, const bf16* __restrict__ ql,
    const bf16* __restrict__ kh, const bf16* __restrict__ kl,
    float* __restrict__ sc)
{
    extern __shared__ char sm[];
    const uint32_t smb = smem_u32(sm);
    const int tid = threadIdx.x, lane = tid & 31, wid = tid >> 5;
    const int z = blockIdx.z, m0 = blockIdx.y * 128, n0 = blockIdx.x * 128;
    const int wm = wid >> 2, wn = wid & 3;
    const size_t zo = (size_t)z * SS * DH;

    #pragma unroll
    for (int t = 0; t < 4; t++) {
        const int i = tid + t * 256;
        const int r = i >> 3, c = i & 7;
        cp16(smb +             r*144 + c*16, qh + zo + (size_t)(m0 + r) * DH + c * 8);
        cp16(smb + 18432 +     r*144 + c*16, ql + zo + (size_t)(m0 + r) * DH + c * 8);
        cp16(smb + 36864 +     r*144 + c*16, kh + zo + (size_t)(n0 + r) * DH + c * 8);
        cp16(smb + 55296 +     r*144 + c*16, kl + zo + (size_t)(n0 + r) * DH + c * 8);
    }
    CP_COMMIT(); CP_WAIT0();
    __syncthreads();

    float acc[4][4][4];
    #pragma unroll
    for (int i = 0; i < 4; i++)
        #pragma unroll
        for (int j = 0; j < 4; j++)
            #pragma unroll
            for (int q = 0; q < 4; q++) acc[i][j][q] = 0.f;

    const uint32_t sA = smb, sAl = smb + 18432, sB = smb + 36864, sBl = smb + 55296;
    #pragma unroll
    for (int ks = 0; ks < 4; ks++) {
        const int kb = ks * 32;
        uint32_t af[4][4], bh_[4][2], bl_[4][2];
        #pragma unroll
        for (int mf = 0; mf < 4; mf++)
            LDSM4(af[mf], sA + (wm*64 + mf*16 + (lane & 15)) * 144 + kb + (lane >> 4) * 16);
        #pragma unroll
        for (int nh = 0; nh < 2; nh++) {
            uint32_t r[4];
            // non-trans B from [N,K] layout
            LDSM4(r, sB + (wn*32 + nh*16 + (lane & 7) + ((lane >> 4) & 1) * 8) * 144
                     + kb + ((lane >> 3) & 1) * 16);
            bh_[nh*2][0]=r[0]; bh_[nh*2][1]=r[1]; bh_[nh*2+1][0]=r[2]; bh_[nh*2+1][1]=r[3];
            LDSM4(r, sBl + (wn*32 + nh*16 + (lane & 7) + ((lane >> 4) & 1) * 8) * 144
                     + kb + ((lane >> 3) & 1) * 16);
            bl_[nh*2][0]=r[0]; bl_[nh*2][1]=r[1]; bl_[nh*2+1][0]=r[2]; bl_[nh*2+1][1]=r[3];
        }
        #pragma unroll
        for (int mf = 0; mf < 4; mf++)
            #pragma unroll
            for (int nf = 0; nf < 4; nf++) MMA(acc[mf][nf], af[mf], bh_[nf]);
        #pragma unroll
        for (int mf = 0; mf < 4; mf++)
            #pragma unroll
            for (int nf = 0; nf < 4; nf++) MMA(acc[mf][nf], af[mf], bl_[nf]);
        #pragma unroll
        for (int mf = 0; mf < 4; mf++)
            LDSM4(af[mf], sAl + (wm*64 + mf*16 + (lane & 15)) * 144 + kb + (lane >> 4) * 16);
        #pragma unroll
        for (int mf = 0; mf < 4; mf++)
            #pragma unroll
            for (int nf = 0; nf < 4; nf++) MMA(acc[mf][nf], af[mf], bh_[nf]);
    }

    float* so = sc + (size_t)z * SS * SS;
    #pragma unroll
    for (int mf = 0; mf < 4; mf++)
        #pragma unroll
        for (int nf = 0; nf < 4; nf++) {
            const int row0 = m0 + wm*64 + mf*16 + (lane >> 2);
            const int col  = n0 + wn*32 + nf*8 + (lane & 3) * 2;
            #pragma unroll
            for (int half = 0; half < 2; half++) {
                const int row = row0 + half * 8;
                *(float2*)(so + (size_t)row * SS + col) =
                    make_float2(acc[mf][nf][half*2] * 0.125f, acc[mf][nf][half*2+1] * 0.125f);
            }
        }
}

// ============================ softmax rows -> split bf16 P ============================
__global__ __launch_bounds__(256) void softmax_kernel(
    const float* __restrict__ sc, bf16* __restrict__ ph, bf16* __restrict__ pl)
{
    __shared__ float redm[8], reds[8];
    const size_t row = blockIdx.x;
    const float* p = sc + row * SS;
    const int tid = threadIdx.x;
    const float4 a = ((const float4*)p)[tid];
    const float4 b = ((const float4*)p)[tid + 256];
    float e[8] = {a.x, a.y, a.z, a.w, b.x, b.y, b.z, b.w};
    float mx = e[0];
    #pragma unroll
    for (int i = 1; i < 8; i++) mx = fmaxf(mx, e[i]);
    #pragma unroll
    for (int o = 16; o; o >>= 1) mx = fmaxf(mx, __shfl_xor_sync(0xffffffffu, mx, o));
    const int w = tid >> 5;
    if ((tid & 31) == 0) redm[w] = mx;
    __syncthreads();
    mx = redm[0];
    #pragma unroll
    for (int i = 1; i < 8; i++) mx = fmaxf(mx, redm[i]);
    float s = 0.f;
    #pragma unroll
    for (int i = 0; i < 8; i++) { e[i] = __expf(e[i] - mx); s += e[i]; }
    #pragma unroll
    for (int o = 16; o; o >>= 1) s += __shfl_xor_sync(0xffffffffu, s, o);
    if ((tid & 31) == 0) reds[w] = s;
    __syncthreads();
    s = 0.f;
    #pragma unroll
    for (int i = 0; i < 8; i++) s += reds[i];
    const float inv = 1.0f / s;
    ushort4 h, l;
    split2(e[0]*inv, h.x, l.x); split2(e[1]*inv, h.y, l.y);
    split2(e[2]*inv, h.z, l.z); split2(e[3]*inv, h.w, l.w);
    *(ushort4*)(ph + row * SS + tid * 4) = h;
    *(ushort4*)(pl + row * SS + tid * 4) = l;
    split2(e[4]*inv, h.x, l.x); split2(e[5]*inv, h.y, l.y);
    split2(e[6]*inv, h.z, l.z); split2(e[7]*inv, h.w, l.w);
    *(ushort4*)(ph + row * SS + 1024 + tid * 4) = h;
    *(ushort4*)(pl + row * SS + 1024 + tid * 4) = l;
}

// ============================ PV GEMM: O = P @ V -> split bf16 into ah/al ============================
// batched z=32; M=2048, N=64, K=2048. Tile 128x64, BK=32, 8 warps (4x2), warp 32x32.
// smem/stage: Ph 128x32 pad80 =10240 | Pl | Vh 32x64 pad144 = 4608 | Vl = 29696
#define PVSTG 29696
#define PV_SMEM (2 * PVSTG)
__global__ __launch_bounds__(256) void pv_mma(
    const bf16* __restrict__ ph, const bf16* __restrict__ pl,
    const bf16* __restrict__ vh, const bf16* __restrict__ vl,
    bf16* __restrict__ ohi, bf16* __restrict__ olo)
{
    extern __shared__ char sm[];
    const uint32_t smb = smem_u32(sm);
    const int tid = threadIdx.x, lane = tid & 31, wid = tid >> 5;
    const int z = blockIdx.z, m0 = blockIdx.y * 128;
    const int wm = wid >> 1, wn = wid & 1;
    const size_t po = (size_t)z * SS * SS;
    const size_t vo = (size_t)z * SS * DH;

    float acc[2][4][4];
    #pragma unroll
    for (int i = 0; i < 2; i++)
        #pragma unroll
        for (int j = 0; j < 4; j++)
            #pragma unroll
            for (int q = 0; q < 4; q++) acc[i][j][q] = 0.f;

    auto load_stage = [&](int s, int buf) {
        const uint32_t sb = smb + buf * PVSTG;
        const int k0 = s << 5;
        #pragma unroll
        for (int t = 0; t < 2; t++) {
            const int i = tid + t * 256;
            const int r = i >> 2, c = i & 3;     // P: 128 rows x 4 chunks
            cp16(sb + r * 80 + c * 16,         ph + po + (size_t)(m0 + r) * SS + k0 + c * 8);
            cp16(sb + 10240 + r * 80 + c * 16, pl + po + (size_t)(m0 + r) * SS + k0 + c * 8);
        }
        { // V: 32 rows x 8 chunks = 256 -> first 256 threads one each
            const int r = tid >> 3, c = tid & 7;
            cp16(sb + 20480 + r * 144 + c * 16,        vh + vo + (size_t)(k0 + r) * DH + c * 8);
            cp16(sb + 20480 + 4608 + r * 144 + c * 16, vl + vo + (size_t)(k0 + r) * DH + c * 8);
        }
        CP_COMMIT();
    };

    const int NSG = SS >> 5;   // 64
    load_stage(0, 0);
    for (int s = 0; s < NSG; s++) {
        const int buf = s & 1;
        if (s + 1 < NSG) { load_stage(s + 1, buf ^ 1); CP_WAIT1(); }
        else             { CP_WAIT0(); }
        __syncthreads();

        const uint32_t sA  = smb + buf * PVSTG;
        const uint32_t sAl = sA + 10240;
        const uint32_t sB  = sA + 20480;
        const uint32_t sBl = sB + 4608;

        #pragma unroll
        for (int ks = 0; ks < 2; ks++) {
            const int kb = ks * 32;
            uint32_t af[2][4], bh_[4][2], bl_[4][2];
            #pragma unroll
            for (int mf = 0; mf < 2; mf++)
                LDSM4(af[mf], sA + (wm*32 + mf*16 + (lane & 15)) * 80 + kb + (lane >> 4) * 16);
            #pragma unroll
            for (int nh = 0; nh < 2; nh++) {
                uint32_t r[4];
                LDSM4T(r, sB + (ks*16 + (lane & 7) + ((lane >> 3) & 1) * 8) * 144
                          + (wn*32 + nh*16) * 2 + (lane >> 4) * 16);
                bh_[nh*2][0]=r[0]; bh_[nh*2][1]=r[1]; bh_[nh*2+1][0]=r[2]; bh_[nh*2+1][1]=r[3];
                LDSM4T(r, sBl + (ks*16 + (lane & 7) + ((lane >> 3) & 1) * 8) * 144
                          + (wn*32 + nh*16) * 2 + (lane >> 4) * 16);
                bl_[nh*2][0]=r[0]; bl_[nh*2][1]=r[1]; bl_[nh*2+1][0]=r[2]; bl_[nh*2+1][1]=r[3];
            }
            #pragma unroll
            for (int mf = 0; mf < 2; mf++)
                #pragma unroll
                for (int nf = 0; nf < 4; nf++) MMA(acc[mf][nf], af[mf], bh_[nf]);
            #pragma unroll
            for (int mf = 0; mf < 2; mf++)
                #pragma unroll
                for (int nf = 0; nf < 4; nf++) MMA(acc[mf][nf], af[mf], bl_[nf]);
            #pragma unroll
            for (int mf = 0; mf < 2; mf++)
                LDSM4(af[mf], sAl + (wm*32 + mf*16 + (lane & 15)) * 80 + kb + (lane >> 4) * 16);
            #pragma unroll
            for (int mf = 0; mf < 2; mf++)
                #pragma unroll
                for (int nf = 0; nf < 4; nf++) MMA(acc[mf][nf], af[mf], bh_[nf]);
        }
        __syncthreads();
    }

    // epilogue: write split bf16 into residual-stream activation layout [row, h*64+d]
    const int bb = z >> 4, hh = z & 15;
    #pragma unroll
    for (int mf = 0; mf < 2; mf++)
        #pragma unroll
        for (int nf = 0; nf < 4; nf++) {
            const int row0 = m0 + wm*32 + mf*16 + (lane >> 2);
            const int col  = wn*32 + nf*8 + (lane & 3) * 2;
            #pragma unroll
            for (int half = 0; half < 2; half++) {
                const int row = row0 + half * 8;
                const size_t off = ((size_t)(bb * SS + row)) * DD + hh * DH + col;
                unsigned short h0,l0,h1,l1;
                split2(acc[mf][nf][half*2],     h0, l0);
                split2(acc[mf][nf][half*2 + 1], h1, l1);
                *(uint32_t*)(ohi + off) = (uint32_t)h0 | ((uint32_t)h1 << 16);
                *(uint32_t*)(olo + off) = (uint32_t)l0 | ((uint32_t)l1 << 16);
            }
        }
}

// ============================ launch ============================
extern "C" void kernel_launch(void* const* d_in, const int* in_sizes, int n_in,
                              void* d_out, int out_size)
{
    const float* x     = (const float*)d_in[0];
    const float* ln1_g = (const float*)d_in[1];
    const float* ln1_b = (const float*)d_in[2];
    const float* w_qkv = (const float*)d_in[3];
    const float* b_qkv = (const float*)d_in[4];
    const float* w_out = (const float*)d_in[5];
    const float* b_out = (const float*)d_in[6];
    const float* ln2_g = (const float*)d_in[7];
    const float* ln2_b = (const float*)d_in[8];
    const float* w1    = (const float*)d_in[9];
    const float* b1    = (const float*)d_in[10];
    const float* w2    = (const float*)d_in[11];
    const float* b2    = (const float*)d_in[12];

    float *scores, *x1;
    bf16 *ph, *pl, *qh, *ql, *kh, *kl, *vh, *vl, *ah, *al, *a2h, *a2l, *bwh, *bwl;
    cudaGetSymbolAddress((void**)&scores, g_scores);
    cudaGetSymbolAddress((void**)&ph, g_ph);   cudaGetSymbolAddress((void**)&pl, g_pl);
    cudaGetSymbolAddress((void**)&qh, g_qh);   cudaGetSymbolAddress((void**)&ql, g_ql);
    cudaGetSymbolAddress((void**)&kh, g_kh);   cudaGetSymbolAddress((void**)&kl, g_kl);
    cudaGetSymbolAddress((void**)&vh, g_vh);   cudaGetSymbolAddress((void**)&vl, g_vl);
    cudaGetSymbolAddress((void**)&x1, g_x1);
    cudaGetSymbolAddress((void**)&ah, g_ah);   cudaGetSymbolAddress((void**)&al, g_al);
    cudaGetSymbolAddress((void**)&a2h, g_a2h); cudaGetSymbolAddress((void**)&a2l, g_a2l);
    cudaGetSymbolAddress((void**)&bwh, g_bwh); cudaGetSymbolAddress((void**)&bwl, g_bwl);

    cudaFuncSetAttribute(gemm_mma<1>, cudaFuncAttributeMaxDynamicSharedMemorySize, GEMM_SMEM);
    cudaFuncSetAttribute(gemm_mma<2>, cudaFuncAttributeMaxDynamicSharedMemorySize, GEMM_SMEM);
    cudaFuncSetAttribute(gemm_mma<3>, cudaFuncAttributeMaxDynamicSharedMemorySize, GEMM_SMEM);
    cudaFuncSetAttribute(scores_mma,  cudaFuncAttributeMaxDynamicSharedMemorySize, SC_SMEM);
    cudaFuncSetAttribute(pv_mma,      cudaFuncAttributeMaxDynamicSharedMemorySize, PV_SMEM);

    // 1) LN1 -> split activations
    ln_split_kernel<<<ROWS, 256>>>(x, ln1_g, ln1_b, ah, al);
    // 2) QKV projection, epilogue scatters split q/k/v per head
    convert_split_kernel<<<(DD*D3)/1024, 256>>>(w_qkv, bwh, bwl);
    gemm_mma<3><<<dim3(D3/128, ROWS/128), 256, GEMM_SMEM>>>(
        ROWS, D3, DD, ah, al, bwh, bwl, b_qkv, nullptr,
        nullptr, nullptr, nullptr, qh, ql, kh, kl, vh, vl);
    // 3) scores + softmax + PV
    scores_mma<<<dim3(SS/128, SS/128, NZ), 256, SC_SMEM>>>(qh, ql, kh, kl, scores);
    softmax_kernel<<<NZ*SS, 256>>>(scores, ph, pl);
    pv_mma<<<dim3(1, SS/128, NZ), 256, PV_SMEM>>>(ph, pl, vh, vl, ah, al);
    // 4) out projection + residual(x) -> x1
    convert_split_kernel<<<(DD*DD)/1024, 256>>>(w_out, bwh, bwl);
    gemm_mma<2><<<dim3(DD/128, ROWS/128), 256, GEMM_SMEM>>>(
        ROWS, DD, DD, ah, al, bwh, bwl, b_out, x,
        x1, nullptr, nullptr, nullptr, nullptr, nullptr, nullptr, nullptr, nullptr);
    // 5) LN2 -> split
    ln_split_kernel<<<ROWS, 256>>>(x1, ln2_g, ln2_b, ah, al);
    // 6) MLP up + GELU -> split bf16
    convert_split_kernel<<<(DD*D4)/1024, 256>>>(w1, bwh, bwl);
    gemm_mma<1><<<dim3(D4/128, ROWS/128), 256, GEMM_SMEM>>>(
        ROWS, D4, DD, ah, al, bwh, bwl, b1, nullptr,
        nullptr, a2h, a2l, nullptr, nullptr, nullptr, nullptr, nullptr, nullptr);
    // 7) MLP down + residual(x1) -> d_out
    convert_split_kernel<<<(D4*DD)/1024, 256>>>(w2, bwh, bwl);
    gemm_mma<2><<<dim3(DD/128, ROWS/128), 256, GEMM_SMEM>>>(
        ROWS, DD, D4, a2h, a2l, bwh, bwl, b2, x1,
        (float*)d_out, nullptr, nullptr, nullptr, nullptr, nullptr, nullptr, nullptr, nullptr);
}

// round 6
// speedup vs baseline: 4.3417x; 1.0885x over previous
#include <cuda_runtime.h>
#include <cuda_bf16.h>
#include <cstdint>

// Problem constants
#define BB 2
#define SS 2048
#define DD 1024
#define HH 16
#define DH 64
#define ROWS (BB*SS)          // 4096
#define D3  (3*DD)            // 3072
#define D4  (4*DD)            // 4096
#define NZ  (BB*HH)           // 32 batched heads

typedef __nv_bfloat16 bf16;

// -------------------- scratch (no allocation allowed) --------------------
__device__ bf16  g_qh[NZ*SS*DH], g_ql[NZ*SS*DH];
__device__ bf16  g_kh[NZ*SS*DH], g_kl[NZ*SS*DH];
__device__ bf16  g_vh[NZ*SS*DH], g_vl[NZ*SS*DH];
__device__ float g_x1 [ROWS*DD];                    // residual stream after attn
__device__ bf16  g_ah [ROWS*DD], g_al [ROWS*DD];    // activation hi/lo
__device__ bf16  g_a2h[ROWS*D4], g_a2l[ROWS*D4];    // GELU out hi/lo
__device__ bf16  g_bwh[DD*D4],  g_bwl[DD*D4];       // weight split

// ==================== PTX helpers (portable sm_80+ subset) ====================
__device__ __forceinline__ uint32_t smem_u32(const void* p) {
    uint32_t a;
    asm("{ .reg .u64 t; cvta.to.shared.u64 t, %1; cvt.u32.u64 %0, t; }" : "=r"(a) : "l"(p));
    return a;
}
__device__ __forceinline__ void cp16(uint32_t s, const void* g) {
    asm volatile("cp.async.cg.shared.global [%0], [%1], 16;" :: "r"(s), "l"(g));
}
#define CP_COMMIT() asm volatile("cp.async.commit_group;" ::: "memory")
#define CP_WAIT0()  asm volatile("cp.async.wait_group 0;" ::: "memory")
#define CP_WAIT1()  asm volatile("cp.async.wait_group 1;" ::: "memory")

#define LDSM4(R, A) \
    asm volatile("ldmatrix.sync.aligned.m8n8.x4.shared.b16 {%0,%1,%2,%3}, [%4];" \
        : "=r"((R)[0]), "=r"((R)[1]), "=r"((R)[2]), "=r"((R)[3]) : "r"(A))
#define LDSM4T(R, A) \
    asm volatile("ldmatrix.sync.aligned.m8n8.x4.trans.shared.b16 {%0,%1,%2,%3}, [%4];" \
        : "=r"((R)[0]), "=r"((R)[1]), "=r"((R)[2]), "=r"((R)[3]) : "r"(A))
#define MMA(C, A, B) \
    asm volatile("mma.sync.aligned.m16n8k16.row.col.f32.bf16.bf16.f32 " \
        "{%0,%1,%2,%3}, {%4,%5,%6,%7}, {%8,%9}, {%0,%1,%2,%3};" \
        : "+f"((C)[0]), "+f"((C)[1]), "+f"((C)[2]), "+f"((C)[3]) \
        : "r"((A)[0]), "r"((A)[1]), "r"((A)[2]), "r"((A)[3]), "r"((B)[0]), "r"((B)[1]))

// ==================== bf16 split helpers ====================
__device__ __forceinline__ uint32_t pack_bf2(float x, float y) {
    __nv_bfloat162 t = __floats2bfloat162_rn(x, y);
    return *reinterpret_cast<uint32_t*>(&t);
}
__device__ __forceinline__ void split2(float v, unsigned short& h, unsigned short& l) {
    bf16 hb = __float2bfloat16(v);
    bf16 lb = __float2bfloat16(v - __bfloat162float(hb));
    h = *reinterpret_cast<unsigned short*>(&hb);
    l = *reinterpret_cast<unsigned short*>(&lb);
}
// split two floats -> packed hi reg + packed lo reg
__device__ __forceinline__ void split_pack2(float x, float y, uint32_t& hi, uint32_t& lo) {
    bf16 hx = __float2bfloat16(x), hy = __float2bfloat16(y);
    float rx = x - __bfloat162float(hx);
    float ry = y - __bfloat162float(hy);
    hi = ((uint32_t)*reinterpret_cast<unsigned short*>(&hx)) |
         ((uint32_t)*reinterpret_cast<unsigned short*>(&hy) << 16);
    lo = pack_bf2(rx, ry);
}
__device__ __forceinline__ float gelu_exact(float x) {
    return 0.5f * x * (1.0f + erff(x * 0.70710678118654752f));
}

// ============================ LayerNorm (fused split output) ============================
__global__ __launch_bounds__(256) void ln_split_kernel(
    const float* __restrict__ x, const float* __restrict__ g,
    const float* __restrict__ b, bf16* __restrict__ ohi, bf16* __restrict__ olo)
{
    __shared__ float red[2][8];
    const int row = blockIdx.x;
    const int tid = threadIdx.x;
    const float4 v = ((const float4*)(x + (size_t)row * DD))[tid];
    float s  = v.x + v.y + v.z + v.w;
    float ss = v.x*v.x + v.y*v.y + v.z*v.z + v.w*v.w;
    #pragma unroll
    for (int o = 16; o; o >>= 1) {
        s  += __shfl_xor_sync(0xffffffffu, s,  o);
        ss += __shfl_xor_sync(0xffffffffu, ss, o);
    }
    const int w = tid >> 5;
    if ((tid & 31) == 0) { red[0][w] = s; red[1][w] = ss; }
    __syncthreads();
    float ts = 0.f, tss = 0.f;
    #pragma unroll
    for (int i = 0; i < 8; i++) { ts += red[0][i]; tss += red[1][i]; }
    const float mu  = ts * (1.0f / DD);
    const float var = tss * (1.0f / DD) - mu * mu;
    const float rs  = rsqrtf(var + 1e-5f);
    const float4 gv = ((const float4*)g)[tid];
    const float4 bv = ((const float4*)b)[tid];
    float o[4];
    o[0] = (v.x - mu) * rs * gv.x + bv.x;
    o[1] = (v.y - mu) * rs * gv.y + bv.y;
    o[2] = (v.z - mu) * rs * gv.z + bv.z;
    o[3] = (v.w - mu) * rs * gv.w + bv.w;
    ushort4 h, l;
    split2(o[0], h.x, l.x); split2(o[1], h.y, l.y);
    split2(o[2], h.z, l.z); split2(o[3], h.w, l.w);
    const size_t idx = (size_t)row * DD + tid * 4;
    *(ushort4*)(ohi + idx) = h;
    *(ushort4*)(olo + idx) = l;
}

// ============================ elementwise fp32 -> hi/lo split ============================
__global__ __launch_bounds__(256) void convert_split_kernel(
    const float* __restrict__ in, bf16* __restrict__ ohi, bf16* __restrict__ olo)
{
    const size_t i = ((size_t)blockIdx.x * 256 + threadIdx.x) * 4;
    const float4 v = *(const float4*)(in + i);
    ushort4 h, l;
    split2(v.x, h.x, l.x); split2(v.y, h.y, l.y);
    split2(v.z, h.z, l.z); split2(v.w, h.w, l.w);
    *(ushort4*)(ohi + i) = h;
    *(ushort4*)(olo + i) = l;
}

// ============================ linear GEMM (mma.sync, split bf16, 3 terms) ============================
#define STG1 37888
#define GEMM_SMEM (2 * STG1)

template<int EPI>
__global__ __launch_bounds__(256) void gemm_mma(
    int M, int N, int K,
    const bf16* __restrict__ Ah, const bf16* __restrict__ Al,
    const bf16* __restrict__ Bh, const bf16* __restrict__ Bl,
    const float* __restrict__ bias, const float* __restrict__ res,
    float* __restrict__ Cf, bf16* __restrict__ Chi, bf16* __restrict__ Clo,
    bf16* __restrict__ qh, bf16* __restrict__ ql,
    bf16* __restrict__ kh, bf16* __restrict__ kl,
    bf16* __restrict__ vh, bf16* __restrict__ vl)
{
    extern __shared__ char sm[];
    const uint32_t smb = smem_u32(sm);
    const int tid = threadIdx.x, lane = tid & 31, wid = tid >> 5;
    const int m0 = blockIdx.y * 128, n0 = blockIdx.x * 128;
    const int wm = wid >> 2, wn = wid & 3;

    float acc[4][4][4];
    #pragma unroll
    for (int i = 0; i < 4; i++)
        #pragma unroll
        for (int j = 0; j < 4; j++)
            #pragma unroll
            for (int q = 0; q < 4; q++) acc[i][j][q] = 0.f;

    const int NSG = K >> 5;

    auto load_stage = [&](int s, int buf) {
        const uint32_t sb = smb + buf * STG1;
        const int k0 = s << 5;
        #pragma unroll
        for (int t = 0; t < 2; t++) {
            const int i = tid + t * 256;
            const int r = i >> 2, c = i & 3;
            cp16(sb + r * 80 + c * 16,          Ah + (size_t)(m0 + r) * K + k0 + c * 8);
            cp16(sb + 10240 + r * 80 + c * 16,  Al + (size_t)(m0 + r) * K + k0 + c * 8);
            const int rb = i >> 4, cb = i & 15;
            cp16(sb + 20480 + rb * 272 + cb * 16,         Bh + (size_t)(k0 + rb) * N + n0 + cb * 8);
            cp16(sb + 20480 + 8704 + rb * 272 + cb * 16,  Bl + (size_t)(k0 + rb) * N + n0 + cb * 8);
        }
        CP_COMMIT();
    };

    load_stage(0, 0);
    for (int s = 0; s < NSG; s++) {
        const int buf = s & 1;
        if (s + 1 < NSG) { load_stage(s + 1, buf ^ 1); CP_WAIT1(); }
        else             { CP_WAIT0(); }
        __syncthreads();

        const uint32_t sA  = smb + buf * STG1;
        const uint32_t sAl = sA + 10240;
        const uint32_t sB  = sA + 20480;
        const uint32_t sBl = sB + 8704;

        #pragma unroll
        for (int ks = 0; ks < 2; ks++) {
            const int kb = ks * 32;
            uint32_t af[4][4], bh_[4][2], bl_[4][2];
            #pragma unroll
            for (int mf = 0; mf < 4; mf++)
                LDSM4(af[mf], sA + (wm*64 + mf*16 + (lane & 15)) * 80 + kb + (lane >> 4) * 16);
            #pragma unroll
            for (int nh = 0; nh < 2; nh++) {
                uint32_t r[4];
                LDSM4T(r, sB + (ks*16 + (lane & 7) + ((lane >> 3) & 1) * 8) * 272
                          + (wn*32 + nh*16) * 2 + (lane >> 4) * 16);
                bh_[nh*2][0]=r[0]; bh_[nh*2][1]=r[1]; bh_[nh*2+1][0]=r[2]; bh_[nh*2+1][1]=r[3];
                LDSM4T(r, sBl + (ks*16 + (lane & 7) + ((lane >> 3) & 1) * 8) * 272
                          + (wn*32 + nh*16) * 2 + (lane >> 4) * 16);
                bl_[nh*2][0]=r[0]; bl_[nh*2][1]=r[1]; bl_[nh*2+1][0]=r[2]; bl_[nh*2+1][1]=r[3];
            }
            #pragma unroll
            for (int mf = 0; mf < 4; mf++)
                #pragma unroll
                for (int nf = 0; nf < 4; nf++) MMA(acc[mf][nf], af[mf], bh_[nf]);
            #pragma unroll
            for (int mf = 0; mf < 4; mf++)
                #pragma unroll
                for (int nf = 0; nf < 4; nf++) MMA(acc[mf][nf], af[mf], bl_[nf]);
            #pragma unroll
            for (int mf = 0; mf < 4; mf++)
                LDSM4(af[mf], sAl + (wm*64 + mf*16 + (lane & 15)) * 80 + kb + (lane >> 4) * 16);
            #pragma unroll
            for (int mf = 0; mf < 4; mf++)
                #pragma unroll
                for (int nf = 0; nf < 4; nf++) MMA(acc[mf][nf], af[mf], bh_[nf]);
        }
        __syncthreads();
    }

    const int r_base = m0 + wm * 64;
    const int c_base = n0 + wn * 32;
    #pragma unroll
    for (int mf = 0; mf < 4; mf++) {
        #pragma unroll
        for (int nf = 0; nf < 4; nf++) {
            const int row0 = r_base + mf*16 + (lane >> 2);
            const int col  = c_base + nf*8 + (lane & 3) * 2;
            const float b0 = bias[col], b1 = bias[col + 1];
            #pragma unroll
            for (int half = 0; half < 2; half++) {
                const int row = row0 + half * 8;
                float v0 = acc[mf][nf][half*2 + 0] + b0;
                float v1 = acc[mf][nf][half*2 + 1] + b1;
                const size_t off = (size_t)row * N + col;
                if (EPI == 1) {
                    v0 = gelu_exact(v0); v1 = gelu_exact(v1);
                    uint32_t hi, lo;
                    split_pack2(v0, v1, hi, lo);
                    *(uint32_t*)(Chi + off) = hi;
                    *(uint32_t*)(Clo + off) = lo;
                } else if (EPI == 2) {
                    const float2 rv = *(const float2*)(res + off);
                    *(float2*)(Cf + off) = make_float2(v0 + rv.x, v1 + rv.y);
                } else { // EPI == 3: qkv head split
                    const int which = n0 >> 10;
                    const int h = (col >> 6) & 15;
                    const int d = col & 63;
                    const int bb = row >> 11, s_ = row & 2047;
                    const size_t doff = ((size_t)(bb * HH + h) * SS + s_) * DH + d;
                    bf16 *dh, *dl;
                    if (which == 0)      { dh = qh; dl = ql; }
                    else if (which == 1) { dh = kh; dl = kl; }
                    else                 { dh = vh; dl = vl; }
                    uint32_t hi, lo;
                    split_pack2(v0, v1, hi, lo);
                    *(uint32_t*)(dh + doff) = hi;
                    *(uint32_t*)(dl + doff) = lo;
                }
            }
        }
    }
}

// ============================ fused flash attention (mma.sync, split bf16) ============================
// grid (SS/128, NZ), 256 threads = 8 warps, warp w owns q rows [w*16, w*16+16).
// smem: Qh/Ql 128x64 pad144 (18432 each) | 2 stages x {Kh,Kl,Vh,Vl} (18432 each)
#define FA_Q    0
#define FA_QL   18432
#define FA_STG0 36864
#define FA_STGS 73728
#define FA_SMEM (FA_STG0 + 2 * FA_STGS)

__global__ __launch_bounds__(256) void flash_mma(
    const bf16* __restrict__ qh, const bf16* __restrict__ ql,
    const bf16* __restrict__ kh, const bf16* __restrict__ kl,
    const bf16* __restrict__ vh, const bf16* __restrict__ vl,
    bf16* __restrict__ ohi, bf16* __restrict__ olo)
{
    extern __shared__ char sm[];
    const uint32_t smb = smem_u32(sm);
    const int tid = threadIdx.x, lane = tid & 31, wid = tid >> 5;
    const int z = blockIdx.y, m0q = blockIdx.x * 128;
    const size_t zo = (size_t)z * SS * DH;

    // ---- load Q tile (both splits) + stage 0 K/V, then stage 1 ----
    auto load_kv = [&](int kt, int buf) {
        const uint32_t sb = smb + FA_STG0 + buf * FA_STGS;
        const int r0 = kt * 128;
        #pragma unroll
        for (int t = 0; t < 4; t++) {
            const int i = tid + t * 256;
            const int r = i >> 3, c = i & 7;
            const size_t go = zo + (size_t)(r0 + r) * DH + c * 8;
            cp16(sb +         r * 144 + c * 16, kh + go);
            cp16(sb + 18432 + r * 144 + c * 16, kl + go);
            cp16(sb + 36864 + r * 144 + c * 16, vh + go);
            cp16(sb + 55296 + r * 144 + c * 16, vl + go);
        }
        CP_COMMIT();
    };

    #pragma unroll
    for (int t = 0; t < 4; t++) {
        const int i = tid + t * 256;
        const int r = i >> 3, c = i & 7;
        const size_t go = zo + (size_t)(m0q + r) * DH + c * 8;
        cp16(smb + FA_Q  + r * 144 + c * 16, qh + go);
        cp16(smb + FA_QL + r * 144 + c * 16, ql + go);
    }
    load_kv(0, 0);   // group 0 = Q + stage0
    load_kv(1, 1);   // group 1 (load_kv commits each)
    CP_WAIT1();      // group 0 (Q + stage0) complete
    __syncthreads();

    // Q fragments (persistent in registers)
    uint32_t qfh[4][4], qfl[4][4];
    #pragma unroll
    for (int ks = 0; ks < 4; ks++) {
        const uint32_t qa = (uint32_t)((wid*16 + (lane & 15)) * 144 + ks*32 + (lane >> 4) * 16);
        LDSM4(qfh[ks], smb + FA_Q  + qa);
        LDSM4(qfl[ks], smb + FA_QL + qa);
    }

    float mrow[2] = {-1e30f, -1e30f}, lrow[2] = {0.f, 0.f};
    float oacc[8][4];
    #pragma unroll
    for (int f = 0; f < 8; f++)
        #pragma unroll
        for (int q = 0; q < 4; q++) oacc[f][q] = 0.f;

    for (int kt = 0; kt < 16; kt++) {
        if (kt < 15) CP_WAIT1(); else CP_WAIT0();
        __syncthreads();
        const uint32_t sK  = smb + FA_STG0 + (kt & 1) * FA_STGS;
        const uint32_t sKl = sK + 18432;
        const uint32_t sV  = sK + 36864;
        const uint32_t sVl = sK + 55296;

        // ---- S = Q K^T (3 split terms) ----
        float sacc[16][4];
        #pragma unroll
        for (int f = 0; f < 16; f++)
            #pragma unroll
            for (int q = 0; q < 4; q++) sacc[f][q] = 0.f;

        #pragma unroll
        for (int nk = 0; nk < 8; nk++) {
            const uint32_t brow = (uint32_t)((nk*16 + (lane & 7) + ((lane >> 4) & 1) * 8) * 144
                                             + ((lane >> 3) & 1) * 16);
            #pragma unroll
            for (int ks = 0; ks < 4; ks++) {
                uint32_t rh[4], rl[4];
                LDSM4(rh, sK  + brow + ks*32);
                LDSM4(rl, sKl + brow + ks*32);
                MMA(sacc[2*nk],   qfh[ks], rh);     MMA(sacc[2*nk+1], qfh[ks], rh + 2);
                MMA(sacc[2*nk],   qfh[ks], rl);     MMA(sacc[2*nk+1], qfh[ks], rl + 2);
                MMA(sacc[2*nk],   qfl[ks], rh);     MMA(sacc[2*nk+1], qfl[ks], rh + 2);
            }
        }

        // ---- online softmax (rows g = lane>>2 and g+8) ----
        float mx0 = -1e30f, mx1 = -1e30f;
        #pragma unroll
        for (int f = 0; f < 16; f++) {
            sacc[f][0] *= 0.125f; sacc[f][1] *= 0.125f;
            sacc[f][2] *= 0.125f; sacc[f][3] *= 0.125f;
            mx0 = fmaxf(mx0, fmaxf(sacc[f][0], sacc[f][1]));
            mx1 = fmaxf(mx1, fmaxf(sacc[f][2], sacc[f][3]));
        }
        mx0 = fmaxf(mx0, __shfl_xor_sync(0xffffffffu, mx0, 1));
        mx0 = fmaxf(mx0, __shfl_xor_sync(0xffffffffu, mx0, 2));
        mx1 = fmaxf(mx1, __shfl_xor_sync(0xffffffffu, mx1, 1));
        mx1 = fmaxf(mx1, __shfl_xor_sync(0xffffffffu, mx1, 2));
        const float mn0 = fmaxf(mrow[0], mx0);
        const float mn1 = fmaxf(mrow[1], mx1);
        const float c0 = __expf(mrow[0] - mn0);
        const float c1 = __expf(mrow[1] - mn1);
        lrow[0] *= c0; lrow[1] *= c1;
        mrow[0] = mn0; mrow[1] = mn1;
        #pragma unroll
        for (int f = 0; f < 8; f++) {
            oacc[f][0] *= c0; oacc[f][1] *= c0;
            oacc[f][2] *= c1; oacc[f][3] *= c1;
        }
        float s0 = 0.f, s1 = 0.f;
        #pragma unroll
        for (int f = 0; f < 16; f++) {
            sacc[f][0] = __expf(sacc[f][0] - mn0);
            sacc[f][1] = __expf(sacc[f][1] - mn0);
            sacc[f][2] = __expf(sacc[f][2] - mn1);
            sacc[f][3] = __expf(sacc[f][3] - mn1);
            s0 += sacc[f][0] + sacc[f][1];
            s1 += sacc[f][2] + sacc[f][3];
        }
        s0 += __shfl_xor_sync(0xffffffffu, s0, 1);
        s0 += __shfl_xor_sync(0xffffffffu, s0, 2);
        s1 += __shfl_xor_sync(0xffffffffu, s1, 1);
        s1 += __shfl_xor_sync(0xffffffffu, s1, 2);
        lrow[0] += s0; lrow[1] += s1;

        // ---- O += P V (P in registers via C->A fragment identity; 3 terms) ----
        #pragma unroll
        for (int kb = 0; kb < 8; kb++) {
            uint32_t pah[4], pal[4];
            split_pack2(sacc[2*kb][0],   sacc[2*kb][1],   pah[0], pal[0]);
            split_pack2(sacc[2*kb][2],   sacc[2*kb][3],   pah[1], pal[1]);
            split_pack2(sacc[2*kb+1][0], sacc[2*kb+1][1], pah[2], pal[2]);
            split_pack2(sacc[2*kb+1][2], sacc[2*kb+1][3], pah[3], pal[3]);
            const uint32_t vrow = (uint32_t)((kb*16 + (lane & 7) + ((lane >> 3) & 1) * 8) * 144
                                             + (lane >> 4) * 16);
            #pragma unroll
            for (int nv = 0; nv < 4; nv++) {
                uint32_t vh4[4], vl4[4];
                LDSM4T(vh4, sV  + vrow + nv*32);
                LDSM4T(vl4, sVl + vrow + nv*32);
                MMA(oacc[2*nv],   pah, vh4);     MMA(oacc[2*nv+1], pah, vh4 + 2);
                MMA(oacc[2*nv],   pah, vl4);     MMA(oacc[2*nv+1], pah, vl4 + 2);
                MMA(oacc[2*nv],   pal, vh4);     MMA(oacc[2*nv+1], pal, vh4 + 2);
            }
        }

        __syncthreads();
        if (kt + 2 < 16) load_kv(kt + 2, kt & 1);
    }

    // ---- epilogue: O /= l, split bf16 into residual-activation layout ----
    const float inv0 = 1.0f / lrow[0];
    const float inv1 = 1.0f / lrow[1];
    const int bb = z >> 4, hh = z & 15;
    const int row0 = m0q + wid*16 + (lane >> 2);
    #pragma unroll
    for (int f = 0; f < 8; f++) {
        const int col = (f >> 1) * 16 + (f & 1) * 8 + (lane & 3) * 2;
        const size_t off0 = ((size_t)(bb * SS + row0))     * DD + hh * DH + col;
        const size_t off1 = ((size_t)(bb * SS + row0 + 8)) * DD + hh * DH + col;
        uint32_t hi, lo;
        split_pack2(oacc[f][0] * inv0, oacc[f][1] * inv0, hi, lo);
        *(uint32_t*)(ohi + off0) = hi;
        *(uint32_t*)(olo + off0) = lo;
        split_pack2(oacc[f][2] * inv1, oacc[f][3] * inv1, hi, lo);
        *(uint32_t*)(ohi + off1) = hi;
        *(uint32_t*)(olo + off1) = lo;
    }
}

// ============================ launch ============================
extern "C" void kernel_launch(void* const* d_in, const int* in_sizes, int n_in,
                              void* d_out, int out_size)
{
    const float* x     = (const float*)d_in[0];
    const float* ln1_g = (const float*)d_in[1];
    const float* ln1_b = (const float*)d_in[2];
    const float* w_qkv = (const float*)d_in[3];
    const float* b_qkv = (const float*)d_in[4];
    const float* w_out = (const float*)d_in[5];
    const float* b_out = (const float*)d_in[6];
    const float* ln2_g = (const float*)d_in[7];
    const float* ln2_b = (const float*)d_in[8];
    const float* w1    = (const float*)d_in[9];
    const float* b1    = (const float*)d_in[10];
    const float* w2    = (const float*)d_in[11];
    const float* b2    = (const float*)d_in[12];

    float *x1;
    bf16 *qh, *ql, *kh, *kl, *vh, *vl, *ah, *al, *a2h, *a2l, *bwh, *bwl;
    cudaGetSymbolAddress((void**)&qh, g_qh);   cudaGetSymbolAddress((void**)&ql, g_ql);
    cudaGetSymbolAddress((void**)&kh, g_kh);   cudaGetSymbolAddress((void**)&kl, g_kl);
    cudaGetSymbolAddress((void**)&vh, g_vh);   cudaGetSymbolAddress((void**)&vl, g_vl);
    cudaGetSymbolAddress((void**)&x1, g_x1);
    cudaGetSymbolAddress((void**)&ah, g_ah);   cudaGetSymbolAddress((void**)&al, g_al);
    cudaGetSymbolAddress((void**)&a2h, g_a2h); cudaGetSymbolAddress((void**)&a2l, g_a2l);
    cudaGetSymbolAddress((void**)&bwh, g_bwh); cudaGetSymbolAddress((void**)&bwl, g_bwl);

    cudaFuncSetAttribute(gemm_mma<1>, cudaFuncAttributeMaxDynamicSharedMemorySize, GEMM_SMEM);
    cudaFuncSetAttribute(gemm_mma<2>, cudaFuncAttributeMaxDynamicSharedMemorySize, GEMM_SMEM);
    cudaFuncSetAttribute(gemm_mma<3>, cudaFuncAttributeMaxDynamicSharedMemorySize, GEMM_SMEM);
    cudaFuncSetAttribute(flash_mma,   cudaFuncAttributeMaxDynamicSharedMemorySize, FA_SMEM);

    // 1) LN1 -> split activations
    ln_split_kernel<<<ROWS, 256>>>(x, ln1_g, ln1_b, ah, al);
    // 2) QKV projection, epilogue scatters split q/k/v per head
    convert_split_kernel<<<(DD*D3)/1024, 256>>>(w_qkv, bwh, bwl);
    gemm_mma<3><<<dim3(D3/128, ROWS/128), 256, GEMM_SMEM>>>(
        ROWS, D3, DD, ah, al, bwh, bwl, b_qkv, nullptr,
        nullptr, nullptr, nullptr, qh, ql, kh, kl, vh, vl);
    // 3) fused flash attention -> split bf16 into ah/al
    flash_mma<<<dim3(SS/128, NZ), 256, FA_SMEM>>>(qh, ql, kh, kl, vh, vl, ah, al);
    // 4) out projection + residual(x) -> x1
    convert_split_kernel<<<(DD*DD)/1024, 256>>>(w_out, bwh, bwl);
    gemm_mma<2><<<dim3(DD/128, ROWS/128), 256, GEMM_SMEM>>>(
        ROWS, DD, DD, ah, al, bwh, bwl, b_out, x,
        x1, nullptr, nullptr, nullptr, nullptr, nullptr, nullptr, nullptr, nullptr);
    // 5) LN2 -> split
    ln_split_kernel<<<ROWS, 256>>>(x1, ln2_g, ln2_b, ah, al);
    // 6) MLP up + GELU -> split bf16
    convert_split_kernel<<<(DD*D4)/1024, 256>>>(w1, bwh, bwl);
    gemm_mma<1><<<dim3(D4/128, ROWS/128), 256, GEMM_SMEM>>>(
        ROWS, D4, DD, ah, al, bwh, bwl, b1, nullptr,
        nullptr, a2h, a2l, nullptr, nullptr, nullptr, nullptr, nullptr, nullptr);
    // 7) MLP down + residual(x1) -> d_out
    convert_split_kernel<<<(D4*DD)/1024, 256>>>(w2, bwh, bwl);
    gemm_mma<2><<<dim3(DD/128, ROWS/128), 256, GEMM_SMEM>>>(
        ROWS, DD, D4, a2h, a2l, bwh, bwl, b2, x1,
        (float*)d_out, nullptr, nullptr, nullptr, nullptr, nullptr, nullptr, nullptr, nullptr);
}